// round 1
// baseline (speedup 1.0000x reference)
#include <cuda_runtime.h>
#include <math.h>

// ---------------------------------------------------------------------------
// Problem constants
//   B=16, L=512, H=1024, G=2, NH=16, DH=64, FF=4096, DM=512, LG=256
// ---------------------------------------------------------------------------

// Scratch (device globals; allocation inside kernel_launch is forbidden)
__device__ float g_q  [32u * 512u * 512u];   // (bG, L, DM) plain layout
__device__ float g_k  [32u * 512u * 512u];
__device__ float g_v  [32u * 512u * 512u];
__device__ float g_att[16u * 512u * 1024u];  // atted (B, L, H)
__device__ float g_mh [16u * 512u * 1024u];  // merge output
__device__ float g_y1 [16u * 512u * 1024u];  // LN1 output
__device__ float g_h1 [8192u * 4096u];       // FFN hidden (relu)
__device__ float g_ff [16u * 512u * 1024u];  // FFN output

// ---------------------------------------------------------------------------
// Generic 128x128x8 fp32 SGEMM, 256 threads, 8x8 accum per thread.
// GATHER_A: A rows are gathered from y with the group-reshuffle mapping
//   (row = bg*512 + l ; bg = g*16 + b ; A[row,k] = y[b, l, g*512 + k])
// RELU: fused max(x,0) in epilogue. Bias always added.
// Requires: M%128==0, N%128==0, K%8==0 (true for all calls here).
// ---------------------------------------------------------------------------
template<bool GATHER_A, bool RELU>
__global__ __launch_bounds__(256, 2)
void sgemm128(const float* __restrict__ A, const float* __restrict__ Bm,
              const float* __restrict__ bias, float* __restrict__ C,
              int M, int N, int K)
{
    __shared__ float As[8][128];
    __shared__ float Bs[8][128];

    const int tid  = threadIdx.x;
    const int row0 = blockIdx.y << 7;
    const int col0 = blockIdx.x << 7;

    const int a_row = tid >> 1;          // 0..127
    const int a_col = (tid & 1) << 2;    // 0 or 4
    const int b_row = tid >> 5;          // 0..7
    const int b_col = (tid & 31) << 2;   // 0..124

    const float* Arow;
    {
        int grow = row0 + a_row;
        if (GATHER_A) {
            int bg = grow >> 9;          // /512
            int l  = grow & 511;
            int b  = bg & 15;
            int g  = bg >> 4;
            Arow = A + (((size_t)b * 512 + (size_t)l) * 1024 + (size_t)g * 512);
        } else {
            Arow = A + (size_t)grow * (size_t)K;
        }
    }
    const float* Bbase = Bm + (size_t)b_row * (size_t)N + col0 + b_col;

    float acc[8][8];
#pragma unroll
    for (int i = 0; i < 8; i++)
#pragma unroll
        for (int j = 0; j < 8; j++) acc[i][j] = 0.f;

    const int ty = tid >> 4;  // 0..15
    const int tx = tid & 15;  // 0..15

    for (int k0 = 0; k0 < K; k0 += 8) {
        float4 av = *(const float4*)(Arow + k0 + a_col);
        float4 bv = *(const float4*)(Bbase + (size_t)k0 * (size_t)N);
        As[a_col + 0][a_row] = av.x;
        As[a_col + 1][a_row] = av.y;
        As[a_col + 2][a_row] = av.z;
        As[a_col + 3][a_row] = av.w;
        *(float4*)&Bs[b_row][b_col] = bv;
        __syncthreads();
#pragma unroll
        for (int kk = 0; kk < 8; kk++) {
            float4 a0 = *(const float4*)&As[kk][ty * 8];
            float4 a1 = *(const float4*)&As[kk][ty * 8 + 4];
            float4 b0 = *(const float4*)&Bs[kk][tx * 8];
            float4 b1 = *(const float4*)&Bs[kk][tx * 8 + 4];
            float ar[8] = {a0.x, a0.y, a0.z, a0.w, a1.x, a1.y, a1.z, a1.w};
            float br[8] = {b0.x, b0.y, b0.z, b0.w, b1.x, b1.y, b1.z, b1.w};
#pragma unroll
            for (int i = 0; i < 8; i++)
#pragma unroll
                for (int j = 0; j < 8; j++)
                    acc[i][j] += ar[i] * br[j];
        }
        __syncthreads();
    }

    float bsr[8];
#pragma unroll
    for (int j = 0; j < 8; j++) bsr[j] = bias[col0 + tx * 8 + j];

#pragma unroll
    for (int i = 0; i < 8; i++) {
        size_t cbase = (size_t)(row0 + ty * 8 + i) * (size_t)N + col0 + tx * 8;
        float4 o0, o1;
        o0.x = acc[i][0] + bsr[0]; o0.y = acc[i][1] + bsr[1];
        o0.z = acc[i][2] + bsr[2]; o0.w = acc[i][3] + bsr[3];
        o1.x = acc[i][4] + bsr[4]; o1.y = acc[i][5] + bsr[5];
        o1.z = acc[i][6] + bsr[6]; o1.w = acc[i][7] + bsr[7];
        if (RELU) {
            o0.x = fmaxf(o0.x, 0.f); o0.y = fmaxf(o0.y, 0.f);
            o0.z = fmaxf(o0.z, 0.f); o0.w = fmaxf(o0.w, 0.f);
            o1.x = fmaxf(o1.x, 0.f); o1.y = fmaxf(o1.y, 0.f);
            o1.z = fmaxf(o1.z, 0.f); o1.w = fmaxf(o1.w, 0.f);
        }
        *(float4*)&C[cbase]     = o0;
        *(float4*)&C[cbase + 4] = o1;
    }
}

// ---------------------------------------------------------------------------
// Fused attention: one block per (bg, head). K/V for the head live in smem
// (pitch 65 floats -> conflict-free for both stride-64 and stride-1 access).
// Head mapping: inner row t uses original seq row l = 2t + (h>>3),
// channels (h&7)*64 + d. Output written straight into atted (B, L, H) layout.
// Mask is per-key only: mvals[k] = mask ? -1e9 : 0 (matches reference).
// Mask dtype (bool-u8 vs int32) is detected on-device.
// ---------------------------------------------------------------------------
#define ATTN_SMEM_FLOATS (256*65*2 + 8*128 + 8*512 + 256)
#define ATTN_SMEM_BYTES  (ATTN_SMEM_FLOATS * 4)

__global__ __launch_bounds__(256)
void attn_kernel(const float* __restrict__ q, const float* __restrict__ k,
                 const float* __restrict__ v, const void* __restrict__ maskp,
                 float* __restrict__ atted)
{
    extern __shared__ float sm[];
    float* Ks    = sm;                  // 256*65
    float* Vs    = Ks + 256 * 65;       // 256*65
    float* qbuf  = Vs + 256 * 65;       // 8 warps * 2 rows * 64
    float* pbuf  = qbuf + 8 * 128;      // 8 warps * 2 rows * 256
    float* mvals = pbuf + 8 * 512;      // 256

    const int bh   = blockIdx.x;
    const int bg   = bh >> 4;
    const int h    = bh & 15;
    const int tid  = threadIdx.x;
    const int lane = tid & 31;
    const int w    = tid >> 5;
    const int lpar  = h >> 3;           // 0/1: even/odd original rows
    const int cbase = (h & 7) << 6;     // channel base within DM

    // --- mask dtype detection (words >1 => byte-packed bools) ---
    unsigned int word = ((const unsigned int*)maskp)[tid];  // 256 words, in-bounds either way
    int is32 = __syncthreads_and(word <= 1u);

    const float* kb = k + (size_t)bg * 512 * 512;
    const float* vb = v + (size_t)bg * 512 * 512;
    const float* qb = q + (size_t)bg * 512 * 512;

    for (int idx = tid; idx < 256 * 64; idx += 256) {
        int t = idx >> 6, d = idx & 63;
        size_t off = (size_t)(2 * t + lpar) * 512 + cbase + d;
        Ks[t * 65 + d] = kb[off];
        Vs[t * 65 + d] = vb[off];
    }
    {
        int b = bg & 15;
        int mv = is32 ? ((const int*)maskp)[b * 256 + tid]
                      : (int)((const unsigned char*)maskp)[b * 256 + tid];
        mvals[tid] = mv ? -1e9f : 0.0f;
    }
    __syncthreads();

    const float scale = 0.125f;  // 1/sqrt(64)
    float* myq = qbuf + w * 128;
    float* myp = pbuf + w * 512;
    const int b = bg & 15;
    const int g = bg >> 4;

    // each warp handles 32 inner rows, two at a time
    for (int tp = w * 32; tp < w * 32 + 32; tp += 2) {
        for (int d = lane; d < 64; d += 32) {
            myq[d]      = qb[(size_t)(2 * tp + lpar) * 512 + cbase + d];
            myq[64 + d] = qb[(size_t)(2 * (tp + 1) + lpar) * 512 + cbase + d];
        }
        __syncwarp();

        float s0[8], s1[8];
#pragma unroll
        for (int jj = 0; jj < 8; jj++) { s0[jj] = 0.f; s1[jj] = 0.f; }

        int krow[8];
#pragma unroll
        for (int jj = 0; jj < 8; jj++) krow[jj] = (lane + 32 * jj) * 65;

#pragma unroll 4
        for (int d = 0; d < 64; d++) {
            float q0 = myq[d];
            float q1 = myq[64 + d];
#pragma unroll
            for (int jj = 0; jj < 8; jj++) {
                float kv = Ks[krow[jj] + d];
                s0[jj] += kv * q0;
                s1[jj] += kv * q1;
            }
        }

        float m0 = -3.0e38f, m1 = -3.0e38f;
#pragma unroll
        for (int jj = 0; jj < 8; jj++) {
            float mv = mvals[lane + 32 * jj];
            s0[jj] = s0[jj] * scale + mv;
            s1[jj] = s1[jj] * scale + mv;
            m0 = fmaxf(m0, s0[jj]);
            m1 = fmaxf(m1, s1[jj]);
        }
#pragma unroll
        for (int o = 16; o; o >>= 1) {
            m0 = fmaxf(m0, __shfl_xor_sync(0xffffffffu, m0, o));
            m1 = fmaxf(m1, __shfl_xor_sync(0xffffffffu, m1, o));
        }
        float sum0 = 0.f, sum1 = 0.f;
#pragma unroll
        for (int jj = 0; jj < 8; jj++) {
            s0[jj] = __expf(s0[jj] - m0);
            s1[jj] = __expf(s1[jj] - m1);
            sum0 += s0[jj];
            sum1 += s1[jj];
        }
#pragma unroll
        for (int o = 16; o; o >>= 1) {
            sum0 += __shfl_xor_sync(0xffffffffu, sum0, o);
            sum1 += __shfl_xor_sync(0xffffffffu, sum1, o);
        }
        float inv0 = 1.f / sum0, inv1 = 1.f / sum1;
#pragma unroll
        for (int jj = 0; jj < 8; jj++) {
            myp[lane + 32 * jj]       = s0[jj] * inv0;
            myp[256 + lane + 32 * jj] = s1[jj] * inv1;
        }
        __syncwarp();

        // ctx: lane owns output dims d=lane and d=lane+32 for both rows
        float o00 = 0.f, o01 = 0.f, o10 = 0.f, o11 = 0.f;
#pragma unroll 8
        for (int kk = 0; kk < 256; kk++) {
            float p0 = myp[kk];
            float p1 = myp[256 + kk];
            float va = Vs[kk * 65 + lane];
            float vb2 = Vs[kk * 65 + lane + 32];
            o00 += p0 * va; o01 += p0 * vb2;
            o10 += p1 * va; o11 += p1 * vb2;
        }

        int lrow0 = 2 * tp + lpar;
        int lrow1 = 2 * (tp + 1) + lpar;
        size_t base0 = ((size_t)b * 512 + lrow0) * 1024 + (size_t)g * 512 + cbase;
        size_t base1 = ((size_t)b * 512 + lrow1) * 1024 + (size_t)g * 512 + cbase;
        atted[base0 + lane]      = o00;
        atted[base0 + lane + 32] = o01;
        atted[base1 + lane]      = o10;
        atted[base1 + lane + 32] = o11;
        __syncwarp();
    }
}

// ---------------------------------------------------------------------------
// Residual-add + LayerNorm over rows of 1024. One block (256 thr) per row.
// ---------------------------------------------------------------------------
__global__ __launch_bounds__(256)
void add_ln_kernel(const float* __restrict__ res, const float* __restrict__ dlt,
                   const float* __restrict__ gamma, const float* __restrict__ beta,
                   float* __restrict__ out)
{
    __shared__ float red[8];
    __shared__ float s_mean, s_inv;
    const int row = blockIdx.x;
    const int tid = threadIdx.x;
    const size_t base = (size_t)row * 1024;

    float x[4];
    float s = 0.f;
#pragma unroll
    for (int i = 0; i < 4; i++) {
        int c = tid + (i << 8);
        x[i] = res[base + c] + dlt[base + c];
        s += x[i];
    }
#pragma unroll
    for (int o = 16; o; o >>= 1) s += __shfl_xor_sync(0xffffffffu, s, o);
    if ((tid & 31) == 0) red[tid >> 5] = s;
    __syncthreads();
    if (tid < 32) {
        float t = (tid < 8) ? red[tid] : 0.f;
#pragma unroll
        for (int o = 4; o; o >>= 1) t += __shfl_xor_sync(0xffffffffu, t, o);
        if (tid == 0) s_mean = t * (1.f / 1024.f);
    }
    __syncthreads();
    const float mean = s_mean;

    float vs = 0.f;
#pragma unroll
    for (int i = 0; i < 4; i++) { float d = x[i] - mean; vs += d * d; }
#pragma unroll
    for (int o = 16; o; o >>= 1) vs += __shfl_xor_sync(0xffffffffu, vs, o);
    if ((tid & 31) == 0) red[tid >> 5] = vs;
    __syncthreads();
    if (tid < 32) {
        float t = (tid < 8) ? red[tid] : 0.f;
#pragma unroll
        for (int o = 4; o; o >>= 1) t += __shfl_xor_sync(0xffffffffu, t, o);
        if (tid == 0) s_inv = rsqrtf(t * (1.f / 1024.f) + 1e-6f);
    }
    __syncthreads();
    const float inv = s_inv;

#pragma unroll
    for (int i = 0; i < 4; i++) {
        int c = tid + (i << 8);
        out[base + c] = (x[i] - mean) * inv * gamma[c] + beta[c];
    }
}

// ---------------------------------------------------------------------------
// Launch
// ---------------------------------------------------------------------------
extern "C" void kernel_launch(void* const* d_in, const int* in_sizes, int n_in,
                              void* d_out, int out_size)
{
    const float* y   = (const float*)d_in[0];
    const void*  msk = d_in[1];
    const float* Wv  = (const float*)d_in[2];
    const float* bv  = (const float*)d_in[3];
    const float* Wk  = (const float*)d_in[4];
    const float* bk  = (const float*)d_in[5];
    const float* Wq  = (const float*)d_in[6];
    const float* bq  = (const float*)d_in[7];
    const float* Wm  = (const float*)d_in[8];
    const float* bm  = (const float*)d_in[9];
    const float* W1  = (const float*)d_in[10];
    const float* b1  = (const float*)d_in[11];
    const float* W2  = (const float*)d_in[12];
    const float* b2  = (const float*)d_in[13];
    const float* g1  = (const float*)d_in[14];
    const float* be1 = (const float*)d_in[15];
    const float* g2  = (const float*)d_in[16];
    const float* be2 = (const float*)d_in[17];
    float* out = (float*)d_out;

    float *q, *k, *v, *att, *mh, *y1, *h1, *ff;
    cudaGetSymbolAddress((void**)&q,   g_q);
    cudaGetSymbolAddress((void**)&k,   g_k);
    cudaGetSymbolAddress((void**)&v,   g_v);
    cudaGetSymbolAddress((void**)&att, g_att);
    cudaGetSymbolAddress((void**)&mh,  g_mh);
    cudaGetSymbolAddress((void**)&y1,  g_y1);
    cudaGetSymbolAddress((void**)&h1,  g_h1);
    cudaGetSymbolAddress((void**)&ff,  g_ff);

    cudaFuncSetAttribute(attn_kernel,
                         cudaFuncAttributeMaxDynamicSharedMemorySize,
                         ATTN_SMEM_BYTES);

    dim3 blk(256);

    // QKV projections: (16384, 512) = gather(y) @ W (512,512) + b
    sgemm128<true,  false><<<dim3(4, 128), blk>>>(y, Wq, bq, q, 16384, 512, 512);
    sgemm128<true,  false><<<dim3(4, 128), blk>>>(y, Wk, bk, k, 16384, 512, 512);
    sgemm128<true,  false><<<dim3(4, 128), blk>>>(y, Wv, bv, v, 16384, 512, 512);

    // Attention (fused scores+softmax+ctx), writes atted layout directly
    attn_kernel<<<512, blk, ATTN_SMEM_BYTES>>>(q, k, v, msk, att);

    // Merge: (8192,1024) @ Wm (1024,1024) + bm
    sgemm128<false, false><<<dim3(8, 64), blk>>>(att, Wm, bm, mh, 8192, 1024, 1024);

    // y1 = LN(y + merge)
    add_ln_kernel<<<8192, blk>>>(y, mh, g1, be1, y1);

    // FFN1: (8192,1024) @ W1 (1024,4096) + b1, relu
    sgemm128<false, true ><<<dim3(32, 64), blk>>>(y1, W1, b1, h1, 8192, 4096, 1024);

    // FFN2 (grouped == contiguous reinterpret): (16384,2048) @ W2 (2048,512) + b2
    sgemm128<false, false><<<dim3(4, 128), blk>>>(h1, W2, b2, ff, 16384, 512, 2048);

    // out = LN(y1 + ff)
    add_ln_kernel<<<8192, blk>>>(y1, ff, g2, be2, out);
}

// round 2
// speedup vs baseline: 2.4070x; 2.4070x over previous
#include <cuda_runtime.h>
#include <math.h>

// ---------------------------------------------------------------------------
// Problem constants: B=16, L=512, H=1024, G=2, NH=16, DH=64, FF=4096,
//                    DM=512, LG=256
// ---------------------------------------------------------------------------

// Scratch (device globals; allocation inside kernel_launch is forbidden)
__device__ float g_q  [32u * 512u * 512u];
__device__ float g_k  [32u * 512u * 512u];
__device__ float g_v  [32u * 512u * 512u];
__device__ float g_att[16u * 512u * 1024u];
__device__ float g_mh [16u * 512u * 1024u];
__device__ float g_y1 [16u * 512u * 1024u];
__device__ float g_h1 [8192u * 4096u];
__device__ float g_ff [16u * 512u * 1024u];

// ---------------------------------------------------------------------------
// tf32 helpers
// ---------------------------------------------------------------------------
__device__ __forceinline__ unsigned f2tf32(float x) {
    unsigned y;
    asm("cvt.rna.tf32.f32 %0, %1;" : "=r"(y) : "f"(x));
    return y;
}

__device__ __forceinline__ void mma_tf32(float* d, const unsigned* a, const unsigned* b) {
    asm volatile(
        "mma.sync.aligned.m16n8k8.row.col.f32.tf32.tf32.f32 "
        "{%0,%1,%2,%3}, {%4,%5,%6,%7}, {%8,%9}, {%0,%1,%2,%3};\n"
        : "+f"(d[0]), "+f"(d[1]), "+f"(d[2]), "+f"(d[3])
        : "r"(a[0]), "r"(a[1]), "r"(a[2]), "r"(a[3]), "r"(b[0]), "r"(b[1]));
}

// ---------------------------------------------------------------------------
// tf32 tensor-core GEMM: 128x128 block tile, K-step 32, 256 threads,
// 8 warps in a 2(M) x 4(N) grid, warp tile 64x32 via m16n8k8 mma.
// Bank-conflict-free smem: A pitch 36 (bank == lane on frag loads),
// B pitch 136 (bank == 8*tig+grp). Double-buffered, reg-staged gmem loads.
// GATHER_A folds the group reshuffle (row -> y[b, l, g*512 + k]).
// Requires M%128==0, N%128==0, K%32==0 (true for all calls here).
// ---------------------------------------------------------------------------
#define AS_STRIDE 36
#define BS_STRIDE 136
#define ASIZE (128 * AS_STRIDE)   // 4608 uints
#define BSIZE (32 * BS_STRIDE)    // 4352 uints
#define GEMM_SMEM_BYTES ((2 * ASIZE + 2 * BSIZE) * 4)  // 71680

template<bool GATHER_A, bool RELU>
__global__ __launch_bounds__(256)
void tgemm(const float* __restrict__ A, const float* __restrict__ Bm,
           const float* __restrict__ bias, float* __restrict__ C,
           int M, int N, int K)
{
    extern __shared__ unsigned sh[];
    unsigned* As = sh;              // 2 * ASIZE
    unsigned* Bs = sh + 2 * ASIZE;  // 2 * BSIZE

    const int tid  = threadIdx.x;
    const int row0 = blockIdx.y << 7;
    const int col0 = blockIdx.x << 7;
    const int lane = tid & 31;
    const int w    = tid >> 5;
    const int wm   = w & 1;    // 0..1  (M)
    const int wn   = w >> 1;   // 0..3  (N)
    const int tig  = lane & 3;
    const int grp  = lane >> 2;

    // --- staging descriptors ---
    const float* aptr[4];
    int acol[4], asto[4];
#pragma unroll
    for (int i = 0; i < 4; i++) {
        int idx = tid + (i << 8);
        int r   = idx >> 3;           // 0..127
        acol[i] = (idx & 7) << 2;     // 0..28
        asto[i] = r * AS_STRIDE + acol[i];
        int grow = row0 + r;
        if (GATHER_A) {
            int bg = grow >> 9, l = grow & 511;
            int b  = bg & 15,  g = bg >> 4;
            aptr[i] = A + (((size_t)b * 512 + l) * 1024 + (size_t)g * 512);
        } else {
            aptr[i] = A + (size_t)grow * (size_t)K;
        }
    }
    const float* bptr[4];
    int bsto[4];
#pragma unroll
    for (int i = 0; i < 4; i++) {
        int idx = tid + (i << 8);
        int kr  = idx >> 5;           // 0..31
        int c4  = (idx & 31) << 2;    // 0..124
        bptr[i] = Bm + (size_t)kr * (size_t)N + col0 + c4;
        bsto[i] = kr * BS_STRIDE + c4;
    }

    float acc[4][4][4];
#pragma unroll
    for (int mi = 0; mi < 4; mi++)
#pragma unroll
        for (int ni = 0; ni < 4; ni++)
#pragma unroll
            for (int j = 0; j < 4; j++) acc[mi][ni][j] = 0.f;

    float4 ra[4], rb[4];
    // prologue: tile 0 -> buf 0
#pragma unroll
    for (int i = 0; i < 4; i++) ra[i] = *(const float4*)(aptr[i] + acol[i]);
#pragma unroll
    for (int i = 0; i < 4; i++) rb[i] = *(const float4*)(bptr[i]);
#pragma unroll
    for (int i = 0; i < 4; i++) {
        unsigned* d = As + asto[i];
        d[0] = f2tf32(ra[i].x); d[1] = f2tf32(ra[i].y);
        d[2] = f2tf32(ra[i].z); d[3] = f2tf32(ra[i].w);
        unsigned* e = Bs + bsto[i];
        e[0] = f2tf32(rb[i].x); e[1] = f2tf32(rb[i].y);
        e[2] = f2tf32(rb[i].z); e[3] = f2tf32(rb[i].w);
    }
    __syncthreads();

    const int nIter = K >> 5;
    for (int it = 0; it < nIter; ++it) {
        const int buf = it & 1;
        const bool more = (it + 1 < nIter);
        if (more) {
            const int koff = (it + 1) << 5;
#pragma unroll
            for (int i = 0; i < 4; i++)
                ra[i] = *(const float4*)(aptr[i] + koff + acol[i]);
#pragma unroll
            for (int i = 0; i < 4; i++)
                rb[i] = *(const float4*)(bptr[i] + (size_t)koff * (size_t)N);
        }

        const unsigned* Ab = As + buf * ASIZE;
        const unsigned* Bb = Bs + buf * BSIZE;
#pragma unroll
        for (int kk = 0; kk < 4; kk++) {
            unsigned af[4][4], bf[4][2];
#pragma unroll
            for (int mi = 0; mi < 4; mi++) {
                const unsigned* p = Ab + ((wm << 6) + (mi << 4) + grp) * AS_STRIDE
                                       + (kk << 3) + tig;
                af[mi][0] = p[0];
                af[mi][1] = p[8 * AS_STRIDE];
                af[mi][2] = p[4];
                af[mi][3] = p[8 * AS_STRIDE + 4];
            }
#pragma unroll
            for (int ni = 0; ni < 4; ni++) {
                const unsigned* p = Bb + ((kk << 3) + tig) * BS_STRIDE
                                       + (wn << 5) + (ni << 3) + grp;
                bf[ni][0] = p[0];
                bf[ni][1] = p[4 * BS_STRIDE];
            }
#pragma unroll
            for (int mi = 0; mi < 4; mi++)
#pragma unroll
                for (int ni = 0; ni < 4; ni++)
                    mma_tf32(acc[mi][ni], af[mi], bf[ni]);
        }

        if (more) {
            unsigned* Ad = As + (buf ^ 1) * ASIZE;
            unsigned* Bd = Bs + (buf ^ 1) * BSIZE;
#pragma unroll
            for (int i = 0; i < 4; i++) {
                unsigned* d = Ad + asto[i];
                d[0] = f2tf32(ra[i].x); d[1] = f2tf32(ra[i].y);
                d[2] = f2tf32(ra[i].z); d[3] = f2tf32(ra[i].w);
                unsigned* e = Bd + bsto[i];
                e[0] = f2tf32(rb[i].x); e[1] = f2tf32(rb[i].y);
                e[2] = f2tf32(rb[i].z); e[3] = f2tf32(rb[i].w);
            }
        }
        __syncthreads();
    }

    // epilogue: bias (+relu), float2 stores
#pragma unroll
    for (int mi = 0; mi < 4; mi++) {
        int r = row0 + (wm << 6) + (mi << 4) + grp;
#pragma unroll
        for (int ni = 0; ni < 4; ni++) {
            int c = col0 + (wn << 5) + (ni << 3) + (tig << 1);
            float2 bv = *(const float2*)&bias[c];
            float2 o0, o1;
            o0.x = acc[mi][ni][0] + bv.x; o0.y = acc[mi][ni][1] + bv.y;
            o1.x = acc[mi][ni][2] + bv.x; o1.y = acc[mi][ni][3] + bv.y;
            if (RELU) {
                o0.x = fmaxf(o0.x, 0.f); o0.y = fmaxf(o0.y, 0.f);
                o1.x = fmaxf(o1.x, 0.f); o1.y = fmaxf(o1.y, 0.f);
            }
            *(float2*)&C[(size_t)r * N + c]       = o0;
            *(float2*)&C[(size_t)(r + 8) * N + c] = o1;
        }
    }
}

// ---------------------------------------------------------------------------
// Fused attention: one block per (bg, head), 512 threads (16 warps).
// K/V for the head live in smem (pitch 65). Head mapping: inner row t uses
// original seq row l = 2t + (h>>3), channels (h&7)*64 + d. Output written
// straight into atted (B, L, H) layout. Mask per-key; dtype auto-detected.
// ---------------------------------------------------------------------------
#define ATTN_THREADS 512
#define ATTN_SMEM_FLOATS (256*65*2 + 16*128 + 16*512 + 256)
#define ATTN_SMEM_BYTES  (ATTN_SMEM_FLOATS * 4)

__global__ __launch_bounds__(ATTN_THREADS)
void attn_kernel(const float* __restrict__ q, const float* __restrict__ k,
                 const float* __restrict__ v, const void* __restrict__ maskp,
                 float* __restrict__ atted)
{
    extern __shared__ float sm[];
    float* Ks    = sm;                  // 256*65
    float* Vs    = Ks + 256 * 65;       // 256*65
    float* qbuf  = Vs + 256 * 65;       // 16 warps * 2 rows * 64
    float* pbuf  = qbuf + 16 * 128;     // 16 warps * 2 rows * 256
    float* mvals = pbuf + 16 * 512;     // 256

    const int bh   = blockIdx.x;
    const int bg   = bh >> 4;
    const int h    = bh & 15;
    const int tid  = threadIdx.x;
    const int lane = tid & 31;
    const int w    = tid >> 5;
    const int lpar  = h >> 3;
    const int cbase = (h & 7) << 6;

    // mask dtype detection (any word > 1 => byte-packed bools)
    unsigned int word = 0u;
    if (tid < 256) word = ((const unsigned int*)maskp)[tid];
    int is32 = __syncthreads_and(word <= 1u);

    const float* kb = k + (size_t)bg * 512 * 512;
    const float* vb = v + (size_t)bg * 512 * 512;
    const float* qb = q + (size_t)bg * 512 * 512;

    for (int idx = tid; idx < 256 * 64; idx += ATTN_THREADS) {
        int t = idx >> 6, d = idx & 63;
        size_t off = (size_t)(2 * t + lpar) * 512 + cbase + d;
        Ks[t * 65 + d] = kb[off];
        Vs[t * 65 + d] = vb[off];
    }
    if (tid < 256) {
        int b = bg & 15;
        int mv = is32 ? ((const int*)maskp)[b * 256 + tid]
                      : (int)((const unsigned char*)maskp)[b * 256 + tid];
        mvals[tid] = mv ? -1e9f : 0.0f;
    }
    __syncthreads();

    const float scale = 0.125f;
    float* myq = qbuf + w * 128;
    float* myp = pbuf + w * 512;
    const int b = bg & 15;
    const int g = bg >> 4;

    for (int tp = w * 16; tp < w * 16 + 16; tp += 2) {
        for (int d = lane; d < 64; d += 32) {
            myq[d]      = qb[(size_t)(2 * tp + lpar) * 512 + cbase + d];
            myq[64 + d] = qb[(size_t)(2 * (tp + 1) + lpar) * 512 + cbase + d];
        }
        __syncwarp();

        float s0[8], s1[8];
#pragma unroll
        for (int jj = 0; jj < 8; jj++) { s0[jj] = 0.f; s1[jj] = 0.f; }

        int krow[8];
#pragma unroll
        for (int jj = 0; jj < 8; jj++) krow[jj] = (lane + 32 * jj) * 65;

#pragma unroll 4
        for (int d = 0; d < 64; d++) {
            float q0 = myq[d];
            float q1 = myq[64 + d];
#pragma unroll
            for (int jj = 0; jj < 8; jj++) {
                float kv = Ks[krow[jj] + d];
                s0[jj] += kv * q0;
                s1[jj] += kv * q1;
            }
        }

        float m0 = -3.0e38f, m1 = -3.0e38f;
#pragma unroll
        for (int jj = 0; jj < 8; jj++) {
            float mv = mvals[lane + 32 * jj];
            s0[jj] = s0[jj] * scale + mv;
            s1[jj] = s1[jj] * scale + mv;
            m0 = fmaxf(m0, s0[jj]);
            m1 = fmaxf(m1, s1[jj]);
        }
#pragma unroll
        for (int o = 16; o; o >>= 1) {
            m0 = fmaxf(m0, __shfl_xor_sync(0xffffffffu, m0, o));
            m1 = fmaxf(m1, __shfl_xor_sync(0xffffffffu, m1, o));
        }
        float sum0 = 0.f, sum1 = 0.f;
#pragma unroll
        for (int jj = 0; jj < 8; jj++) {
            s0[jj] = __expf(s0[jj] - m0);
            s1[jj] = __expf(s1[jj] - m1);
            sum0 += s0[jj];
            sum1 += s1[jj];
        }
#pragma unroll
        for (int o = 16; o; o >>= 1) {
            sum0 += __shfl_xor_sync(0xffffffffu, sum0, o);
            sum1 += __shfl_xor_sync(0xffffffffu, sum1, o);
        }
        float inv0 = 1.f / sum0, inv1 = 1.f / sum1;
#pragma unroll
        for (int jj = 0; jj < 8; jj++) {
            myp[lane + 32 * jj]       = s0[jj] * inv0;
            myp[256 + lane + 32 * jj] = s1[jj] * inv1;
        }
        __syncwarp();

        float o00 = 0.f, o01 = 0.f, o10 = 0.f, o11 = 0.f;
#pragma unroll 8
        for (int kk = 0; kk < 256; kk++) {
            float p0 = myp[kk];
            float p1 = myp[256 + kk];
            float va  = Vs[kk * 65 + lane];
            float vb2 = Vs[kk * 65 + lane + 32];
            o00 += p0 * va; o01 += p0 * vb2;
            o10 += p1 * va; o11 += p1 * vb2;
        }

        int lrow0 = 2 * tp + lpar;
        int lrow1 = 2 * (tp + 1) + lpar;
        size_t base0 = ((size_t)b * 512 + lrow0) * 1024 + (size_t)g * 512 + cbase;
        size_t base1 = ((size_t)b * 512 + lrow1) * 1024 + (size_t)g * 512 + cbase;
        atted[base0 + lane]      = o00;
        atted[base0 + lane + 32] = o01;
        atted[base1 + lane]      = o10;
        atted[base1 + lane + 32] = o11;
        __syncwarp();
    }
}

// ---------------------------------------------------------------------------
// Residual-add + LayerNorm over rows of 1024. One block (256 thr) per row.
// ---------------------------------------------------------------------------
__global__ __launch_bounds__(256)
void add_ln_kernel(const float* __restrict__ res, const float* __restrict__ dlt,
                   const float* __restrict__ gamma, const float* __restrict__ beta,
                   float* __restrict__ out)
{
    __shared__ float red[8];
    __shared__ float s_mean, s_inv;
    const int row = blockIdx.x;
    const int tid = threadIdx.x;
    const size_t base = (size_t)row * 1024;

    float x[4];
    float s = 0.f;
#pragma unroll
    for (int i = 0; i < 4; i++) {
        int c = tid + (i << 8);
        x[i] = res[base + c] + dlt[base + c];
        s += x[i];
    }
#pragma unroll
    for (int o = 16; o; o >>= 1) s += __shfl_xor_sync(0xffffffffu, s, o);
    if ((tid & 31) == 0) red[tid >> 5] = s;
    __syncthreads();
    if (tid < 32) {
        float t = (tid < 8) ? red[tid] : 0.f;
#pragma unroll
        for (int o = 4; o; o >>= 1) t += __shfl_xor_sync(0xffffffffu, t, o);
        if (tid == 0) s_mean = t * (1.f / 1024.f);
    }
    __syncthreads();
    const float mean = s_mean;

    float vs = 0.f;
#pragma unroll
    for (int i = 0; i < 4; i++) { float d = x[i] - mean; vs += d * d; }
#pragma unroll
    for (int o = 16; o; o >>= 1) vs += __shfl_xor_sync(0xffffffffu, vs, o);
    if ((tid & 31) == 0) red[tid >> 5] = vs;
    __syncthreads();
    if (tid < 32) {
        float t = (tid < 8) ? red[tid] : 0.f;
#pragma unroll
        for (int o = 4; o; o >>= 1) t += __shfl_xor_sync(0xffffffffu, t, o);
        if (tid == 0) s_inv = rsqrtf(t * (1.f / 1024.f) + 1e-6f);
    }
    __syncthreads();
    const float inv = s_inv;

#pragma unroll
    for (int i = 0; i < 4; i++) {
        int c = tid + (i << 8);
        out[base + c] = (x[i] - mean) * inv * gamma[c] + beta[c];
    }
}

// ---------------------------------------------------------------------------
// Launch
// ---------------------------------------------------------------------------
extern "C" void kernel_launch(void* const* d_in, const int* in_sizes, int n_in,
                              void* d_out, int out_size)
{
    const float* y   = (const float*)d_in[0];
    const void*  msk = d_in[1];
    const float* Wv  = (const float*)d_in[2];
    const float* bv  = (const float*)d_in[3];
    const float* Wk  = (const float*)d_in[4];
    const float* bk  = (const float*)d_in[5];
    const float* Wq  = (const float*)d_in[6];
    const float* bq  = (const float*)d_in[7];
    const float* Wm  = (const float*)d_in[8];
    const float* bm  = (const float*)d_in[9];
    const float* W1  = (const float*)d_in[10];
    const float* b1  = (const float*)d_in[11];
    const float* W2  = (const float*)d_in[12];
    const float* b2  = (const float*)d_in[13];
    const float* g1  = (const float*)d_in[14];
    const float* be1 = (const float*)d_in[15];
    const float* g2  = (const float*)d_in[16];
    const float* be2 = (const float*)d_in[17];
    float* out = (float*)d_out;

    float *q, *k, *v, *att, *mh, *y1, *h1, *ff;
    cudaGetSymbolAddress((void**)&q,   g_q);
    cudaGetSymbolAddress((void**)&k,   g_k);
    cudaGetSymbolAddress((void**)&v,   g_v);
    cudaGetSymbolAddress((void**)&att, g_att);
    cudaGetSymbolAddress((void**)&mh,  g_mh);
    cudaGetSymbolAddress((void**)&y1,  g_y1);
    cudaGetSymbolAddress((void**)&h1,  g_h1);
    cudaGetSymbolAddress((void**)&ff,  g_ff);

    cudaFuncSetAttribute(attn_kernel,
                         cudaFuncAttributeMaxDynamicSharedMemorySize,
                         ATTN_SMEM_BYTES);
    cudaFuncSetAttribute(tgemm<true,  false>,
                         cudaFuncAttributeMaxDynamicSharedMemorySize, GEMM_SMEM_BYTES);
    cudaFuncSetAttribute(tgemm<false, false>,
                         cudaFuncAttributeMaxDynamicSharedMemorySize, GEMM_SMEM_BYTES);
    cudaFuncSetAttribute(tgemm<false, true>,
                         cudaFuncAttributeMaxDynamicSharedMemorySize, GEMM_SMEM_BYTES);

    dim3 blk(256);

    // QKV projections: (16384, 512) = gather(y) @ W (512,512) + b
    tgemm<true,  false><<<dim3(4, 128), blk, GEMM_SMEM_BYTES>>>(y, Wq, bq, q, 16384, 512, 512);
    tgemm<true,  false><<<dim3(4, 128), blk, GEMM_SMEM_BYTES>>>(y, Wk, bk, k, 16384, 512, 512);
    tgemm<true,  false><<<dim3(4, 128), blk, GEMM_SMEM_BYTES>>>(y, Wv, bv, v, 16384, 512, 512);

    // Attention (fused scores+softmax+ctx) -> atted layout directly
    attn_kernel<<<512, ATTN_THREADS, ATTN_SMEM_BYTES>>>(q, k, v, msk, att);

    // Merge: (8192,1024) @ Wm (1024,1024) + bm
    tgemm<false, false><<<dim3(8, 64), blk, GEMM_SMEM_BYTES>>>(att, Wm, bm, mh, 8192, 1024, 1024);

    // y1 = LN(y + merge)
    add_ln_kernel<<<8192, blk>>>(y, mh, g1, be1, y1);

    // FFN1: (8192,1024) @ W1 (1024,4096) + b1, relu
    tgemm<false, true ><<<dim3(32, 64), blk, GEMM_SMEM_BYTES>>>(y1, W1, b1, h1, 8192, 4096, 1024);

    // FFN2 (grouped == contiguous reinterpret): (16384,2048) @ W2 (2048,512) + b2
    tgemm<false, false><<<dim3(4, 128), blk, GEMM_SMEM_BYTES>>>(h1, W2, b2, ff, 16384, 512, 2048);

    // out = LN(y1 + ff)
    add_ln_kernel<<<8192, blk>>>(y1, ff, g2, be2, out);
}

// round 3
// speedup vs baseline: 3.3014x; 1.3716x over previous
#include <cuda_runtime.h>
#include <math.h>

// ---------------------------------------------------------------------------
// Problem constants: B=16, L=512, H=1024, G=2, NH=16, DH=64, FF=4096,
//                    DM=512, LG=256
// ---------------------------------------------------------------------------

// Scratch (device globals; allocation inside kernel_launch is forbidden)
__device__ float g_yc [16u*512u*1024u];   // tf32-rounded copy of y
__device__ float g_wq [512u*512u];
__device__ float g_wk [512u*512u];
__device__ float g_wv [512u*512u];
__device__ float g_wm [1024u*1024u];
__device__ float g_w1 [1024u*4096u];
__device__ float g_w2 [2048u*512u];
__device__ float g_q  [32u*512u*512u];
__device__ float g_k  [32u*512u*512u];
__device__ float g_v  [32u*512u*512u];
__device__ float g_att[16u*512u*1024u];
__device__ float g_mh [16u*512u*1024u];
__device__ float g_y1 [16u*512u*1024u];
__device__ float g_h1 [8192u*4096u];
__device__ float g_ff [16u*512u*1024u];

// ---------------------------------------------------------------------------
// tf32 / cp.async helpers
// ---------------------------------------------------------------------------
__device__ __forceinline__ unsigned f2tf32(float x) {
    unsigned y;
    asm("cvt.rna.tf32.f32 %0, %1;" : "=r"(y) : "f"(x));
    return y;
}
__device__ __forceinline__ float tf32_round(float x) {
    return __uint_as_float(f2tf32(x));
}

__device__ __forceinline__ void mma_tf32(float* d, const unsigned* a, const unsigned* b) {
    asm volatile(
        "mma.sync.aligned.m16n8k8.row.col.f32.tf32.tf32.f32 "
        "{%0,%1,%2,%3}, {%4,%5,%6,%7}, {%8,%9}, {%0,%1,%2,%3};\n"
        : "+f"(d[0]), "+f"(d[1]), "+f"(d[2]), "+f"(d[3])
        : "r"(a[0]), "r"(a[1]), "r"(a[2]), "r"(a[3]), "r"(b[0]), "r"(b[1]));
}

__device__ __forceinline__ void cp16(unsigned dst, const void* src) {
    asm volatile("cp.async.cg.shared.global [%0], [%1], 16;\n" :: "r"(dst), "l"(src));
}
__device__ __forceinline__ void cp_commit() {
    asm volatile("cp.async.commit_group;\n" ::);
}
template<int N>
__device__ __forceinline__ void cp_wait() {
    asm volatile("cp.async.wait_group %0;\n" :: "n"(N));
}

// ---------------------------------------------------------------------------
// Elementwise tf32 rounding (pre-pass for y and weights)
// ---------------------------------------------------------------------------
__global__ void cvt_arr(const float* __restrict__ in, float* __restrict__ out, int n)
{
    int i = blockIdx.x * blockDim.x + threadIdx.x;
    int stride = gridDim.x * blockDim.x;
    for (; i < n; i += stride) out[i] = tf32_round(in[i]);
}

// ---------------------------------------------------------------------------
// tf32 tensor-core GEMM: 128x256 block tile, K-step 32, 256 threads,
// 8 warps in 2(M) x 4(N), warp tile 64x64 via m16n8k8 mma.
// 3-stage cp.async pipeline, inputs pre-rounded to tf32 (no cvt in kernel).
// A smem pitch 36 (banks grp*4+tig: conflict-free), B pitch 264 (banks
// tig*8+grp: conflict-free). GATHER_A folds the group reshuffle.
// Requires M%128==0, N%256==0, K%32==0.
// ---------------------------------------------------------------------------
#define BK 32
#define STAGES 3
#define APITCH 36
#define BPITCH 264
#define AWORDS (128 * APITCH)          // 4608
#define BWORDS (BK * BPITCH)           // 8448
#define STAGEW (AWORDS + BWORDS)       // 13056
#define AB_OFF (AWORDS * 4)
#define GEMM_SMEM_BYTES (STAGES * STAGEW * 4)   // 156672

#define GEMM_ISSUE(s_) do {                                                   \
    int k0_ = (s_) << 5;                                                      \
    unsigned sb_ = sbase + (unsigned)(((s_) % STAGES) * (STAGEW * 4));        \
    _Pragma("unroll")                                                         \
    for (int i_ = 0; i_ < 4; i_++) cp16(sb_ + a_sm[i_], a_gm[i_] + k0_);      \
    _Pragma("unroll")                                                         \
    for (int i_ = 0; i_ < 8; i_++)                                            \
        cp16(sb_ + AB_OFF + b_sm[i_], b_gm[i_] + (size_t)k0_ * (size_t)N);    \
} while (0)

template<bool GATHER_A, bool RELU, bool CVT_OUT>
__global__ __launch_bounds__(256, 1)
void tgemm(const float* __restrict__ A, const float* __restrict__ Bm,
           const float* __restrict__ bias, float* __restrict__ C,
           int M, int N, int K)
{
    extern __shared__ unsigned sh[];
    const unsigned sbase = (unsigned)__cvta_generic_to_shared(sh);

    const int tid  = threadIdx.x;
    const int row0 = blockIdx.y << 7;
    const int col0 = blockIdx.x << 8;
    const int lane = tid & 31;
    const int w    = tid >> 5;
    const int wm   = w & 1;     // 0..1 (M)
    const int wn   = w >> 1;    // 0..3 (N)
    const int tig  = lane & 3;
    const int grp  = lane >> 2;

    // A copy descriptors: 4 x 16B chunks per thread (128x32 tile)
    unsigned a_sm[4];
    const float* a_gm[4];
#pragma unroll
    for (int i = 0; i < 4; i++) {
        int c  = tid + (i << 8);      // 0..1023
        int r  = c >> 3;              // row 0..127
        int kc = (c & 7) << 2;        // 0..28
        a_sm[i] = (unsigned)((r * APITCH + kc) * 4);
        int grow = row0 + r;
        if (GATHER_A) {
            int bg = grow >> 9, l = grow & 511;
            int b  = bg & 15,  g = bg >> 4;
            a_gm[i] = A + (((size_t)b * 512 + l) * 1024 + (size_t)g * 512) + kc;
        } else {
            a_gm[i] = A + (size_t)grow * (size_t)K + kc;
        }
    }
    // B copy descriptors: 8 x 16B chunks per thread (32x256 tile)
    unsigned b_sm[8];
    const float* b_gm[8];
#pragma unroll
    for (int i = 0; i < 8; i++) {
        int c  = tid + (i << 8);      // 0..2047
        int kr = c >> 6;              // 0..31
        int nc = (c & 63) << 2;       // 0..252
        b_sm[i] = (unsigned)((kr * BPITCH + nc) * 4);
        b_gm[i] = Bm + (size_t)kr * (size_t)N + col0 + nc;
    }

    float acc[4][8][4];
#pragma unroll
    for (int mi = 0; mi < 4; mi++)
#pragma unroll
        for (int ni = 0; ni < 8; ni++)
#pragma unroll
            for (int j = 0; j < 4; j++) acc[mi][ni][j] = 0.f;

    GEMM_ISSUE(0); cp_commit();
    GEMM_ISSUE(1); cp_commit();

    const int nIter = K >> 5;
    for (int it = 0; it < nIter; ++it) {
        cp_wait<1>();
        __syncthreads();

        const unsigned* Ab = sh + (it % STAGES) * STAGEW;
        const unsigned* Bb = Ab + AWORDS;
#pragma unroll
        for (int kk = 0; kk < 4; kk++) {
            unsigned af[4][4], bf[8][2];
#pragma unroll
            for (int mi = 0; mi < 4; mi++) {
                const unsigned* p = Ab + ((wm << 6) + (mi << 4) + grp) * APITCH
                                       + (kk << 3) + tig;
                af[mi][0] = p[0];
                af[mi][1] = p[8 * APITCH];
                af[mi][2] = p[4];
                af[mi][3] = p[8 * APITCH + 4];
            }
#pragma unroll
            for (int ni = 0; ni < 8; ni++) {
                const unsigned* p = Bb + ((kk << 3) + tig) * BPITCH
                                       + (wn << 6) + (ni << 3) + grp;
                bf[ni][0] = p[0];
                bf[ni][1] = p[4 * BPITCH];
            }
#pragma unroll
            for (int mi = 0; mi < 4; mi++)
#pragma unroll
                for (int ni = 0; ni < 8; ni++)
                    mma_tf32(acc[mi][ni], af[mi], bf[ni]);
        }

        int s = it + 2;
        if (s < nIter) GEMM_ISSUE(s);
        cp_commit();
    }

    // epilogue: bias (+relu) (+tf32 rounding), float2 stores
#pragma unroll
    for (int mi = 0; mi < 4; mi++) {
        int r = row0 + (wm << 6) + (mi << 4) + grp;
#pragma unroll
        for (int ni = 0; ni < 8; ni++) {
            int c = col0 + (wn << 6) + (ni << 3) + (tig << 1);
            float2 bv = *(const float2*)&bias[c];
            float v00 = acc[mi][ni][0] + bv.x;
            float v01 = acc[mi][ni][1] + bv.y;
            float v10 = acc[mi][ni][2] + bv.x;
            float v11 = acc[mi][ni][3] + bv.y;
            if (RELU) {
                v00 = fmaxf(v00, 0.f); v01 = fmaxf(v01, 0.f);
                v10 = fmaxf(v10, 0.f); v11 = fmaxf(v11, 0.f);
            }
            if (CVT_OUT) {
                v00 = tf32_round(v00); v01 = tf32_round(v01);
                v10 = tf32_round(v10); v11 = tf32_round(v11);
            }
            float2 o0; o0.x = v00; o0.y = v01;
            float2 o1; o1.x = v10; o1.y = v11;
            *(float2*)&C[(size_t)r * N + c]       = o0;
            *(float2*)&C[(size_t)(r + 8) * N + c] = o1;
        }
    }
}

// ---------------------------------------------------------------------------
// Fused attention: grid = 1024 blocks = (bg, head, row-half), 256 threads.
// K/V for the head in smem (pitch 65). Each warp handles 16 query rows in
// two 8-row passes (high FMA:LDS ratio). Output written into atted (B,L,H)
// layout, tf32-rounded (it feeds the merge GEMM). Mask dtype auto-detected.
// ---------------------------------------------------------------------------
#define ATTN_THREADS 256
#define ATTN_SMEM_FLOATS (256*65*2 + 8*512 + 8*2048 + 256)
#define ATTN_SMEM_BYTES  (ATTN_SMEM_FLOATS * 4)   // 216064

__global__ __launch_bounds__(ATTN_THREADS)
void attn_kernel(const float* __restrict__ q, const float* __restrict__ k,
                 const float* __restrict__ v, const void* __restrict__ maskp,
                 float* __restrict__ atted)
{
    extern __shared__ float sm[];
    float* Ks    = sm;                   // 256*65
    float* Vs    = Ks + 256 * 65;        // 256*65
    float* qb    = Vs + 256 * 65;        // 8 warps * 8 rows * 64
    float* pb    = qb + 8 * 512;         // 8 warps * 8 rows * 256
    float* mvals = pb + 8 * 2048;        // 256

    const int bh   = blockIdx.x >> 1;
    const int half = blockIdx.x & 1;
    const int bg   = bh >> 4;
    const int h    = bh & 15;
    const int tid  = threadIdx.x;
    const int lane = tid & 31;
    const int w    = tid >> 5;
    const int lpar  = h >> 3;
    const int cbase = (h & 7) << 6;

    // mask dtype detection (any word > 1 => byte-packed bools)
    unsigned int word = ((const unsigned int*)maskp)[tid];
    int is32 = __syncthreads_and(word <= 1u);

    const float* kb = k + (size_t)bg * 512 * 512;
    const float* vb = v + (size_t)bg * 512 * 512;
    const float* qp = q + (size_t)bg * 512 * 512;

    // load K/V (float4 gmem, scalar smem stores due to pitch 65)
    for (int idx = tid; idx < 4096; idx += ATTN_THREADS) {
        int t  = idx >> 4;
        int d4 = (idx & 15) << 2;
        size_t off = (size_t)(2 * t + lpar) * 512 + cbase + d4;
        float4 kk4 = *(const float4*)(kb + off);
        float4 vv4 = *(const float4*)(vb + off);
        float* kd = &Ks[t * 65 + d4];
        kd[0] = kk4.x; kd[1] = kk4.y; kd[2] = kk4.z; kd[3] = kk4.w;
        float* vd = &Vs[t * 65 + d4];
        vd[0] = vv4.x; vd[1] = vv4.y; vd[2] = vv4.z; vd[3] = vv4.w;
    }
    {
        int b = bg & 15;
        int mv = is32 ? ((const int*)maskp)[b * 256 + tid]
                      : (int)((const unsigned char*)maskp)[b * 256 + tid];
        mvals[tid] = mv ? -1e9f : 0.0f;
    }
    __syncthreads();

    const float scale = 0.125f;   // 1/sqrt(64)
    float* myq = qb + w * 512;
    float* myp = pb + w * 2048;
    const int b = bg & 15;
    const int g = bg >> 4;
    const int rbase = half * 128 + w * 16;

    float mv[8];
#pragma unroll
    for (int jj = 0; jj < 8; jj++) mv[jj] = mvals[lane + 32 * jj];

    for (int pass = 0; pass < 2; pass++) {
        const int rp = rbase + pass * 8;     // first of 8 query rows

        // load q strip (8 rows x 64)
        for (int idx = lane; idx < 512; idx += 32) {
            int rr = idx >> 6, d = idx & 63;
            myq[idx] = qp[(size_t)(2 * (rp + rr) + lpar) * 512 + cbase + d];
        }
        __syncwarp();

        float s[8][8];
#pragma unroll
        for (int rr = 0; rr < 8; rr++)
#pragma unroll
            for (int jj = 0; jj < 8; jj++) s[rr][jj] = 0.f;

#pragma unroll 2
        for (int d = 0; d < 64; d++) {
            float kv[8];
#pragma unroll
            for (int jj = 0; jj < 8; jj++)
                kv[jj] = Ks[(lane + 32 * jj) * 65 + d];
#pragma unroll
            for (int rr = 0; rr < 8; rr++) {
                float qv = myq[rr * 64 + d];
#pragma unroll
                for (int jj = 0; jj < 8; jj++)
                    s[rr][jj] += kv[jj] * qv;
            }
        }

        // softmax per row
#pragma unroll
        for (int rr = 0; rr < 8; rr++) {
            float m = -3.0e38f;
#pragma unroll
            for (int jj = 0; jj < 8; jj++) {
                s[rr][jj] = s[rr][jj] * scale + mv[jj];
                m = fmaxf(m, s[rr][jj]);
            }
#pragma unroll
            for (int o = 16; o; o >>= 1)
                m = fmaxf(m, __shfl_xor_sync(0xffffffffu, m, o));
            float sum = 0.f;
#pragma unroll
            for (int jj = 0; jj < 8; jj++) {
                s[rr][jj] = __expf(s[rr][jj] - m);
                sum += s[rr][jj];
            }
#pragma unroll
            for (int o = 16; o; o >>= 1)
                sum += __shfl_xor_sync(0xffffffffu, sum, o);
            float inv = 1.f / sum;
#pragma unroll
            for (int jj = 0; jj < 8; jj++)
                myp[rr * 256 + lane + 32 * jj] = s[rr][jj] * inv;
        }
        __syncwarp();

        // ctx: lane owns dims (lane, lane+32) for all 8 rows
        float o0[8], o1[8];
#pragma unroll
        for (int rr = 0; rr < 8; rr++) { o0[rr] = 0.f; o1[rr] = 0.f; }
#pragma unroll 4
        for (int kk = 0; kk < 256; kk++) {
            float va = Vs[kk * 65 + lane];
            float vb2 = Vs[kk * 65 + lane + 32];
#pragma unroll
            for (int rr = 0; rr < 8; rr++) {
                float p = myp[rr * 256 + kk];
                o0[rr] += p * va;
                o1[rr] += p * vb2;
            }
        }

#pragma unroll
        for (int rr = 0; rr < 8; rr++) {
            int l = 2 * (rp + rr) + lpar;
            size_t base = ((size_t)b * 512 + l) * 1024 + (size_t)g * 512 + cbase;
            atted[base + lane]      = tf32_round(o0[rr]);
            atted[base + lane + 32] = tf32_round(o1[rr]);
        }
        __syncwarp();
    }
}

// ---------------------------------------------------------------------------
// Residual-add + LayerNorm over rows of 1024. One block (256 thr) per row.
// cvt_out: round result to tf32 (when it feeds a GEMM).
// ---------------------------------------------------------------------------
__global__ __launch_bounds__(256)
void add_ln_kernel(const float* __restrict__ res, const float* __restrict__ dlt,
                   const float* __restrict__ gamma, const float* __restrict__ beta,
                   float* __restrict__ out, int cvt_out)
{
    __shared__ float red[8];
    __shared__ float s_mean, s_inv;
    const int row = blockIdx.x;
    const int tid = threadIdx.x;
    const size_t base = (size_t)row * 1024;

    float x[4];
    float s = 0.f;
#pragma unroll
    for (int i = 0; i < 4; i++) {
        int c = tid + (i << 8);
        x[i] = res[base + c] + dlt[base + c];
        s += x[i];
    }
#pragma unroll
    for (int o = 16; o; o >>= 1) s += __shfl_xor_sync(0xffffffffu, s, o);
    if ((tid & 31) == 0) red[tid >> 5] = s;
    __syncthreads();
    if (tid < 32) {
        float t = (tid < 8) ? red[tid] : 0.f;
#pragma unroll
        for (int o = 4; o; o >>= 1) t += __shfl_xor_sync(0xffffffffu, t, o);
        if (tid == 0) s_mean = t * (1.f / 1024.f);
    }
    __syncthreads();
    const float mean = s_mean;

    float vs = 0.f;
#pragma unroll
    for (int i = 0; i < 4; i++) { float d = x[i] - mean; vs += d * d; }
#pragma unroll
    for (int o = 16; o; o >>= 1) vs += __shfl_xor_sync(0xffffffffu, vs, o);
    if ((tid & 31) == 0) red[tid >> 5] = vs;
    __syncthreads();
    if (tid < 32) {
        float t = (tid < 8) ? red[tid] : 0.f;
#pragma unroll
        for (int o = 4; o; o >>= 1) t += __shfl_xor_sync(0xffffffffu, t, o);
        if (tid == 0) s_inv = rsqrtf(t * (1.f / 1024.f) + 1e-6f);
    }
    __syncthreads();
    const float inv = s_inv;

#pragma unroll
    for (int i = 0; i < 4; i++) {
        int c = tid + (i << 8);
        float v = (x[i] - mean) * inv * gamma[c] + beta[c];
        out[base + c] = cvt_out ? tf32_round(v) : v;
    }
}

// ---------------------------------------------------------------------------
// Launch
// ---------------------------------------------------------------------------
extern "C" void kernel_launch(void* const* d_in, const int* in_sizes, int n_in,
                              void* d_out, int out_size)
{
    const float* y   = (const float*)d_in[0];
    const void*  msk = d_in[1];
    const float* Wv  = (const float*)d_in[2];
    const float* bv  = (const float*)d_in[3];
    const float* Wk  = (const float*)d_in[4];
    const float* bk  = (const float*)d_in[5];
    const float* Wq  = (const float*)d_in[6];
    const float* bq  = (const float*)d_in[7];
    const float* Wm  = (const float*)d_in[8];
    const float* bm  = (const float*)d_in[9];
    const float* W1  = (const float*)d_in[10];
    const float* b1  = (const float*)d_in[11];
    const float* W2  = (const float*)d_in[12];
    const float* b2  = (const float*)d_in[13];
    const float* g1  = (const float*)d_in[14];
    const float* be1 = (const float*)d_in[15];
    const float* g2  = (const float*)d_in[16];
    const float* be2 = (const float*)d_in[17];
    float* out = (float*)d_out;

    float *yc, *wq, *wk, *wv, *wm, *w1, *w2;
    float *q, *k, *v, *att, *mh, *y1, *h1, *ff;
    cudaGetSymbolAddress((void**)&yc,  g_yc);
    cudaGetSymbolAddress((void**)&wq,  g_wq);
    cudaGetSymbolAddress((void**)&wk,  g_wk);
    cudaGetSymbolAddress((void**)&wv,  g_wv);
    cudaGetSymbolAddress((void**)&wm,  g_wm);
    cudaGetSymbolAddress((void**)&w1,  g_w1);
    cudaGetSymbolAddress((void**)&w2,  g_w2);
    cudaGetSymbolAddress((void**)&q,   g_q);
    cudaGetSymbolAddress((void**)&k,   g_k);
    cudaGetSymbolAddress((void**)&v,   g_v);
    cudaGetSymbolAddress((void**)&att, g_att);
    cudaGetSymbolAddress((void**)&mh,  g_mh);
    cudaGetSymbolAddress((void**)&y1,  g_y1);
    cudaGetSymbolAddress((void**)&h1,  g_h1);
    cudaGetSymbolAddress((void**)&ff,  g_ff);

    cudaFuncSetAttribute(attn_kernel,
                         cudaFuncAttributeMaxDynamicSharedMemorySize, ATTN_SMEM_BYTES);
    cudaFuncSetAttribute(tgemm<true,  false, true >,
                         cudaFuncAttributeMaxDynamicSharedMemorySize, GEMM_SMEM_BYTES);
    cudaFuncSetAttribute(tgemm<false, false, false>,
                         cudaFuncAttributeMaxDynamicSharedMemorySize, GEMM_SMEM_BYTES);
    cudaFuncSetAttribute(tgemm<false, true,  true >,
                         cudaFuncAttributeMaxDynamicSharedMemorySize, GEMM_SMEM_BYTES);

    dim3 blk(256);

    // Pre-round GEMM inputs to tf32 (rna) so raw-bit mma operands are exact
    cvt_arr<<<2048, 512>>>(y,  yc, 16*512*1024);
    cvt_arr<<<512,  512>>>(Wq, wq, 512*512);
    cvt_arr<<<512,  512>>>(Wk, wk, 512*512);
    cvt_arr<<<512,  512>>>(Wv, wv, 512*512);
    cvt_arr<<<1024, 512>>>(Wm, wm, 1024*1024);
    cvt_arr<<<2048, 512>>>(W1, w1, 1024*4096);
    cvt_arr<<<1024, 512>>>(W2, w2, 2048*512);

    // QKV projections: (16384, 512) = gather(yc) @ W (512,512) + b
    tgemm<true,  false, true ><<<dim3(2, 128), blk, GEMM_SMEM_BYTES>>>(yc, wq, bq, q, 16384, 512, 512);
    tgemm<true,  false, true ><<<dim3(2, 128), blk, GEMM_SMEM_BYTES>>>(yc, wk, bk, k, 16384, 512, 512);
    tgemm<true,  false, true ><<<dim3(2, 128), blk, GEMM_SMEM_BYTES>>>(yc, wv, bv, v, 16384, 512, 512);

    // Attention (fused scores+softmax+ctx) -> atted layout, tf32-rounded
    attn_kernel<<<1024, ATTN_THREADS, ATTN_SMEM_BYTES>>>(q, k, v, msk, att);

    // Merge: (8192,1024) @ Wm (1024,1024) + bm
    tgemm<false, false, false><<<dim3(4, 64), blk, GEMM_SMEM_BYTES>>>(att, wm, bm, mh, 8192, 1024, 1024);

    // y1 = LN(y + merge), rounded to tf32 (feeds FFN1)
    add_ln_kernel<<<8192, blk>>>(y, mh, g1, be1, y1, 1);

    // FFN1: (8192,1024) @ W1 (1024,4096) + b1, relu, tf32-rounded
    tgemm<false, true,  true ><<<dim3(16, 64), blk, GEMM_SMEM_BYTES>>>(y1, w1, b1, h1, 8192, 4096, 1024);

    // FFN2 (grouped == contiguous reinterpret): (16384,2048) @ W2 (2048,512) + b2
    tgemm<false, false, false><<<dim3(2, 128), blk, GEMM_SMEM_BYTES>>>(h1, w2, b2, ff, 16384, 512, 2048);

    // out = LN(y1 + ff), full fp32
    add_ln_kernel<<<8192, blk>>>(y1, ff, g2, be2, out, 0);
}